// round 8
// baseline (speedup 1.0000x reference)
#include <cuda_runtime.h>
#include <math.h>
#include <stdint.h>
#include <stddef.h>

#define NB 8
#define LL 2048
#define NL (NB*LL)

// ---------------- device scratch (no allocations allowed) ----------------
static __device__ float4 g_qpack[NL];   // {qx,qy,qz, 0.5*|q|^2 * log2e}
static __device__ float4 g_ppack[NL];   // {px,py,pz, 0.5*|p|^2 * log2e}
static __device__ float  g_f[NL];
static __device__ float  g_g[NL];
static __device__ float  g_spart[4*NL]; // per-quarter row partial sums
static __device__ int    g_ctr[256];    // per-rowgroup arrival counters (zero-init)
static __device__ float  g_cnt[NB];
static __device__ float  g_loga[NB];
static __device__ float  g_cp[NB][3];
static __device__ float  g_ct[NB][3];
static __device__ float  g_R[NB][9];

#define L2E  1.4426950408889634f
#define LN2  0.6931471805599453f
#define E005M1 0.05127109637602412f   // exp(0.05)-1
#define E005   1.0512710963760241f    // exp(0.05)

__device__ __forceinline__ float ex2f_(float x){ float r; asm("ex2.approx.ftz.f32 %0,%1;" : "=f"(r) : "f"(x)); return r; }
__device__ __forceinline__ float lg2f_(float x){ float r; asm("lg2.approx.ftz.f32 %0,%1;" : "=f"(r) : "f"(x)); return r; }

// exp2 on the fma/alu pipes (no MUFU). Round-to-nearest magic split, then
// degree-4 Taylor of 2^f on f in [-0.5, 0.5] (max rel err ~4.2e-5), then
// exponent insertion: bits(p) + (bits(t) << 23). The bias term cancels
// exactly because (0x4B400000 << 23) == 0 mod 2^32.
__device__ __forceinline__ float pexp2(float x){
    x = fmaxf(x, -120.0f);                       // keep result exponent in range
    float t  = __fadd_rn(x, 12582912.0f);        // n = round(x) in low mantissa
    float tt = __fadd_rn(t, -12582912.0f);       // n as float
    float f  = __fadd_rn(x, -tt);                // f in [-0.5, 0.5]
    float p  = fmaf(fmaf(fmaf(fmaf(9.61812911e-3f, f, 5.55041087e-2f),
                              f, 2.40226507e-1f),
                         f, 6.93147181e-1f),
                    f, 1.0f);                    // 2^f
    return __int_as_float(__float_as_int(p) + (__float_as_int(t) << 23));
}

// ---------------- prep ----------------
__global__ void k_zero(){ if (threadIdx.x < NB) g_cnt[threadIdx.x] = 0.f; }

__global__ void k_prep(const float* __restrict__ pred, const float* __restrict__ tru,
                       const float* __restrict__ mgen){
    int t = blockIdx.x*256 + threadIdx.x;   // 0..NL-1
    float px = pred[3*t+0], py = pred[3*t+1], pz = pred[3*t+2];
    float qx = tru [3*t+0], qy = tru [3*t+1], qz = tru [3*t+2];
    g_ppack[t] = make_float4(px,py,pz, 0.5f*(px*px+py*py+pz*pz)*L2E);
    g_qpack[t] = make_float4(qx,qy,qz, 0.5f*(qx*qx+qy*qy+qz*qz)*L2E);
    g_g[t] = 0.f;
    __shared__ float sred[256];
    sred[threadIdx.x] = (mgen[t] != 0.f) ? 1.f : 0.f;
    __syncthreads();
    for (int s = 128; s > 0; s >>= 1){
        if (threadIdx.x < s) sred[threadIdx.x] += sred[threadIdx.x+s];
        __syncthreads();
    }
    if (threadIdx.x == 0) atomicAdd(&g_cnt[blockIdx.x>>3], sred[0]);  // 8 blocks per batch
}

__global__ void k_prep2(){
    if (threadIdx.x < NB) g_loga[threadIdx.x] = -logf(fmaxf(g_cnt[threadIdx.x], 1.f));
}

// ---------------- sinkhorn half-update (hybrid MUFU + poly exp) ----------------
// dir==0: f-update (cols = true/g, rows = pred, out = f)
// dir==1: g-update (cols = pred/f, rows = true, out = g)
// Block: 256 threads (8 warps), 64 rows x 512 cols; lane = row (2 rows/lane),
// warp = 64-col chunk. Even col pairs use MUFU ex2; odd pairs use the
// fma-pipe polynomial exp2 -> both pipes loaded, ~1.5-2x elem rate.
__global__ void __launch_bounds__(256) k_upd(int dir){
    __shared__ float4 tile[512];
    __shared__ float  part[64][9];
    __shared__ int    lastflag;

    const float4* colpack = dir ? g_ppack : g_qpack;
    const float*  colval  = dir ? g_f     : g_g;
    const float4* rowpack = dir ? g_qpack : g_ppack;
    float*        outv    = dir ? g_g     : g_f;

    int b   = blockIdx.x;
    int qtr = b & 3;                 // column quarter
    int rg  = b >> 2;                // rowgroup 0..255
    int n   = rg >> 5;               // 32 rowgroups per batch
    int row0 = (rg & 31) << 6;       // 64 rows per group
    int c0   = qtr << 9;             // 512 cols per quarter

    int tid = threadIdx.x, warp = tid >> 5, lane = tid & 31;

    const float4* cp = colpack + n*LL + c0;
    const float*  cv = colval  + n*LL + c0;
    #pragma unroll
    for (int i = tid; i < 512; i += 256){
        float4 c = cp[i];
        c.w = cv[i]*L2E - c.w;       // log2e*(val - 0.5|v|^2)
        tile[i] = c;
    }

    int r0 = row0 + lane, r1 = row0 + 32 + lane;
    float4 pa = rowpack[n*LL + r0];
    float4 pb = rowpack[n*LL + r1];
    float ax = pa.x*L2E, ay = pa.y*L2E, az = pa.z*L2E;
    float bx = pb.x*L2E, by = pb.y*L2E, bz = pb.z*L2E;

    __syncthreads();

    const float4* tp = tile + (warp << 6);       // 64 cols per warp
    float s00=0.f, s01=0.f, s10=0.f, s11=0.f;
    #pragma unroll 4
    for (int m = 0; m < 64; m += 4){
        // cols m, m+1: MUFU exp
        float4 c0v = tp[m], c1v = tp[m+1];
        s00 += ex2f_(fmaf(ax,c0v.x, fmaf(ay,c0v.y, fmaf(az,c0v.z, c0v.w))));
        s10 += ex2f_(fmaf(bx,c0v.x, fmaf(by,c0v.y, fmaf(bz,c0v.z, c0v.w))));
        s01 += ex2f_(fmaf(ax,c1v.x, fmaf(ay,c1v.y, fmaf(az,c1v.z, c1v.w))));
        s11 += ex2f_(fmaf(bx,c1v.x, fmaf(by,c1v.y, fmaf(bz,c1v.z, c1v.w))));
        // cols m+2, m+3: fma-pipe polynomial exp
        float4 c2v = tp[m+2], c3v = tp[m+3];
        s00 += pexp2(fmaf(ax,c2v.x, fmaf(ay,c2v.y, fmaf(az,c2v.z, c2v.w))));
        s10 += pexp2(fmaf(bx,c2v.x, fmaf(by,c2v.y, fmaf(bz,c2v.z, c2v.w))));
        s01 += pexp2(fmaf(ax,c3v.x, fmaf(ay,c3v.y, fmaf(az,c3v.z, c3v.w))));
        s11 += pexp2(fmaf(bx,c3v.x, fmaf(by,c3v.y, fmaf(bz,c3v.z, c3v.w))));
    }
    part[lane][warp]    = s00 + s01;
    part[32+lane][warp] = s10 + s11;
    __syncthreads();

    if (warp < 2){
        int rr = (warp << 5) + lane;             // 0..63 row within group
        int r  = row0 + rr;                      // row within batch
        float S = 0.f;
        #pragma unroll
        for (int j = 0; j < 8; j++) S += part[rr][j];
        // diagonal bias correction: cost had -0.1 on diag => M has -0.05
        int cl = r - c0;
        if ((unsigned)cl < 512u){
            float4 cd = tile[cl];
            float dx = warp ? bx : ax;
            float dy = warp ? by : ay;
            float dz = warp ? bz : az;
            S += ex2f_(fmaf(dx, cd.x, fmaf(dy, cd.y, fmaf(dz, cd.z, cd.w)))) * E005M1;
        }
        __stcg(&g_spart[qtr*NL + n*LL + r], S);
    }
    __threadfence();
    __syncthreads();
    if (tid == 0){
        int old = atomicAdd(&g_ctr[rg], 1);
        lastflag = (old == 3);
    }
    __syncthreads();
    if (lastflag && warp < 2){
        int rr = (warp << 5) + lane;
        int gidx = n*LL + row0 + rr;
        float S = __ldcg(&g_spart[gidx])
                + __ldcg(&g_spart[NL   + gidx])
                + __ldcg(&g_spart[2*NL + gidx])
                + __ldcg(&g_spart[3*NL + gidx]);
        S = fmaxf(S, 1e-30f);
        float pw = rowpack[gidx].w;
        // out = log_a + 0.5|row|^2 - ln(S)
        outv[gidx] = g_loga[n] + pw*LN2 - LN2*lg2f_(S);
        if (tid == 0) g_ctr[rg] = 0;             // reset for next launch
    }
}

// ---------------- pi + true_pos_mapped ----------------
__global__ void __launch_bounds__(512) k_pi(float* __restrict__ piout, float* __restrict__ tpmout){
    __shared__ float4 tile[LL];
    int n    = blockIdx.x >> 7;          // 128 blocks per batch (16 rows each)
    int row0 = (blockIdx.x & 127) << 4;
    int tid  = threadIdx.x;

    const float4* qp = g_qpack + n*LL;
    const float*  gg = g_g     + n*LL;
    for (int i = tid; i < LL; i += 512){
        float4 c = qp[i];
        c.w = gg[i]*L2E - c.w;
        tile[i] = c;
    }
    __syncthreads();

    int warp = tid >> 5, lane = tid & 31;
    int l = row0 + warp;
    float4 pp = g_ppack[n*LL + l];
    float fp2 = g_f[n*LL + l]*L2E - pp.w;
    float ppx = pp.x*L2E, ppy = pp.y*L2E, ppz = pp.z*L2E;

    float tx=0.f, ty=0.f, tz=0.f;
    float* po = piout + ((size_t)n*LL + l)*LL;
    #pragma unroll 4
    for (int m = lane; m < LL; m += 32){
        float4 c = tile[m];
        float pv = ex2f_(fp2 + fmaf(ppx,c.x, fmaf(ppy,c.y, fmaf(ppz,c.z, c.w))));
        if (m == l) pv *= E005;
        po[m] = pv;
        tx = fmaf(pv, c.x, tx);
        ty = fmaf(pv, c.y, ty);
        tz = fmaf(pv, c.z, tz);
    }
    #pragma unroll
    for (int o = 16; o; o >>= 1){
        tx += __shfl_xor_sync(0xFFFFFFFFu, tx, o);
        ty += __shfl_xor_sync(0xFFFFFFFFu, ty, o);
        tz += __shfl_xor_sync(0xFFFFFFFFu, tz, o);
    }
    if (lane == 0){
        float* tp = tpmout + (size_t)(n*LL + l)*3;
        tp[0] = tx; tp[1] = ty; tp[2] = tz;
    }
}

// ---------------- Kabsch + 3x3 SVD (per batch) ----------------
__global__ void k_kabsch(const float* __restrict__ pred, const float* __restrict__ tpm){
    int n = blockIdx.x, tid = threadIdx.x;
    float s[15];
    #pragma unroll
    for (int k = 0; k < 15; k++) s[k] = 0.f;
    for (int l = tid; l < LL; l += 256){
        const float* p = pred + (size_t)(n*LL + l)*3;
        const float* q = tpm  + (size_t)(n*LL + l)*3;
        float p0=p[0],p1=p[1],p2=p[2], q0=q[0],q1=q[1],q2=q[2];
        s[0]+=p0; s[1]+=p1; s[2]+=p2; s[3]+=q0; s[4]+=q1; s[5]+=q2;
        s[6]+=p0*q0;  s[7]+=p0*q1;  s[8]+=p0*q2;
        s[9]+=p1*q0;  s[10]+=p1*q1; s[11]+=p1*q2;
        s[12]+=p2*q0; s[13]+=p2*q1; s[14]+=p2*q2;
    }
    __shared__ float red[256];
    __shared__ float tot[15];
    for (int k = 0; k < 15; k++){
        red[tid] = s[k]; __syncthreads();
        for (int st = 128; st; st >>= 1){
            if (tid < st) red[tid] += red[tid+st];
            __syncthreads();
        }
        if (tid == 0) tot[k] = red[0];
        __syncthreads();
    }
    if (tid != 0) return;

    double w = fmax((double)g_cnt[n], 1e-6);
    double cp[3] = { tot[0]/w, tot[1]/w, tot[2]/w };
    double cq[3] = { tot[3]/w, tot[4]/w, tot[5]/w };
    double H[3][3];
    for (int i = 0; i < 3; i++)
        for (int j = 0; j < 3; j++)
            H[i][j] = (double)tot[6 + 3*i + j] - w*cp[i]*cq[j];

    double fn = 0.0;
    for (int i = 0; i < 3; i++) for (int j = 0; j < 3; j++) fn += H[i][j]*H[i][j];
    fn = fmax(sqrt(fn), 1e-8);
    double M[3][3];
    for (int i = 0; i < 3; i++)
        for (int j = 0; j < 3; j++)
            M[i][j] = H[i][j]/fn + (i==j ? 1e-4 : 0.0);

    double B[3][3];
    for (int i = 0; i < 3; i++)
        for (int j = 0; j < 3; j++){
            double acc = 0.0;
            for (int k = 0; k < 3; k++) acc += M[k][i]*M[k][j];
            B[i][j] = acc;
        }
    double V[3][3] = {{1,0,0},{0,1,0},{0,0,1}};
    for (int sw = 0; sw < 15; sw++){
        for (int pair = 0; pair < 3; pair++){
            int p = (pair==2) ? 1 : 0;
            int q = (pair==0) ? 1 : 2;
            double apq = B[p][q];
            if (fabs(apq) < 1e-30) continue;
            double tau = (B[q][q] - B[p][p])/(2.0*apq);
            double t = ((tau >= 0.0) ? 1.0 : -1.0)/(fabs(tau) + sqrt(1.0 + tau*tau));
            double c = 1.0/sqrt(1.0 + t*t), sn = t*c;
            for (int k = 0; k < 3; k++){
                double bkp = B[k][p], bkq = B[k][q];
                B[k][p] = c*bkp - sn*bkq; B[k][q] = sn*bkp + c*bkq;
            }
            for (int k = 0; k < 3; k++){
                double bpk = B[p][k], bqk = B[q][k];
                B[p][k] = c*bpk - sn*bqk; B[q][k] = sn*bpk + c*bqk;
            }
            for (int k = 0; k < 3; k++){
                double vkp = V[k][p], vkq = V[k][q];
                V[k][p] = c*vkp - sn*vkq; V[k][q] = sn*vkp + c*vkq;
            }
        }
    }
    double lam[3] = { B[0][0], B[1][1], B[2][2] };
    for (int i = 0; i < 2; i++)
        for (int j = 0; j < 2 - i; j++)
            if (lam[j] < lam[j+1]){
                double tl = lam[j]; lam[j] = lam[j+1]; lam[j+1] = tl;
                for (int k = 0; k < 3; k++){ double tv = V[k][j]; V[k][j] = V[k][j+1]; V[k][j+1] = tv; }
            }
    double detV = V[0][0]*(V[1][1]*V[2][2]-V[1][2]*V[2][1])
                - V[0][1]*(V[1][0]*V[2][2]-V[1][2]*V[2][0])
                + V[0][2]*(V[1][0]*V[2][1]-V[1][1]*V[2][0]);
    if (detV < 0.0) for (int k = 0; k < 3; k++) V[k][2] = -V[k][2];

    double s1 = sqrt(fmax(lam[0], 0.0)), s2 = sqrt(fmax(lam[1], 0.0));
    double u1[3], u2[3], u3[3];
    for (int k = 0; k < 3; k++){
        u1[k] = (M[k][0]*V[0][0] + M[k][1]*V[1][0] + M[k][2]*V[2][0]) / fmax(s1, 1e-30);
        u2[k] = (M[k][0]*V[0][1] + M[k][1]*V[1][1] + M[k][2]*V[2][1]) / fmax(s2, 1e-30);
    }
    double n1 = sqrt(u1[0]*u1[0]+u1[1]*u1[1]+u1[2]*u1[2]);
    for (int k = 0; k < 3; k++) u1[k] /= fmax(n1, 1e-30);
    double d12 = u1[0]*u2[0]+u1[1]*u2[1]+u1[2]*u2[2];
    for (int k = 0; k < 3; k++) u2[k] -= d12*u1[k];
    double n2 = sqrt(u2[0]*u2[0]+u2[1]*u2[1]+u2[2]*u2[2]);
    for (int k = 0; k < 3; k++) u2[k] /= fmax(n2, 1e-30);
    u3[0] = u1[1]*u2[2] - u1[2]*u2[1];
    u3[1] = u1[2]*u2[0] - u1[0]*u2[2];
    u3[2] = u1[0]*u2[1] - u1[1]*u2[0];

    for (int d = 0; d < 3; d++)
        for (int e = 0; e < 3; e++)
            g_R[n][3*d + e] = (float)(u1[d]*V[e][0] + u2[d]*V[e][1] + u3[d]*V[e][2]);
    for (int k = 0; k < 3; k++){ g_cp[n][k] = (float)cp[k]; g_ct[n][k] = (float)cq[k]; }
}

// ---------------- TM score ----------------
__global__ void k_tm(const float* __restrict__ pred, const float* __restrict__ mgen,
                     const float* __restrict__ tpm, float* __restrict__ avg, float inv_d02){
    int n = blockIdx.x, tid = threadIdx.x;
    float R[9];
    #pragma unroll
    for (int k = 0; k < 9; k++) R[k] = g_R[n][k];
    float cp0 = g_cp[n][0], cp1 = g_cp[n][1], cp2 = g_cp[n][2];
    float ct0 = g_ct[n][0], ct1 = g_ct[n][1], ct2 = g_ct[n][2];

    float st = 0.f, sm = 0.f;
    for (int l = tid; l < LL; l += 256){
        const float* p = pred + (size_t)(n*LL + l)*3;
        const float* q = tpm  + (size_t)(n*LL + l)*3;
        float x0 = p[0]-cp0, x1 = p[1]-cp1, x2 = p[2]-cp2;
        float a0 = x0*R[0] + x1*R[3] + x2*R[6] + ct0;
        float a1 = x0*R[1] + x1*R[4] + x2*R[7] + ct1;
        float a2 = x0*R[2] + x1*R[5] + x2*R[8] + ct2;
        float d0 = a0-q[0], d1 = a1-q[1], d2 = a2-q[2];
        float dsq = d0*d0 + d1*d1 + d2*d2;
        float tm = 1.f/(1.f + dsq*inv_d02);
        float mg = mgen[n*LL + l];
        st += tm*mg; sm += mg;
    }
    __shared__ float r1[256], r2[256];
    r1[tid] = st; r2[tid] = sm; __syncthreads();
    for (int s = 128; s; s >>= 1){
        if (tid < s){ r1[tid] += r1[tid+s]; r2[tid] += r2[tid+s]; }
        __syncthreads();
    }
    if (tid == 0) avg[n] = r1[0] / fmaxf(r2[0], 1e-6f);
}

// ---------------- launch ----------------
extern "C" void kernel_launch(void* const* d_in, const int* in_sizes, int n_in,
                              void* d_out, int out_size){
    const float* pred = (const float*)d_in[0];
    const float* tru  = (const float*)d_in[1];
    const float* mgen = (const float*)d_in[2];

    float* out   = (float*)d_out;
    float* avg   = out;                       // (N,)
    float* tpm   = out + NB;                  // (N,L,3)
    float* piout = out + NB + (size_t)NL*3;   // (N,L,L)

    k_zero<<<1, 32>>>();
    k_prep<<<NL/256, 256>>>(pred, tru, mgen);
    k_prep2<<<1, 32>>>();

    for (int it = 0; it < 10; it++){
        k_upd<<<1024, 256>>>(0);   // f-update
        k_upd<<<1024, 256>>>(1);   // g-update
    }

    k_pi<<<1024, 512>>>(piout, tpm);
    k_kabsch<<<NB, 256>>>(pred, tpm);

    double d0 = 1.24 * cbrt((double)((LL > 16 ? LL : 16) - 15)) - 1.8;
    if (d0 < 0.5) d0 = 0.5;
    float inv_d02 = (float)(1.0/(d0*d0));
    k_tm<<<NB, 256>>>(pred, mgen, tpm, avg, inv_d02);
}

// round 9
// speedup vs baseline: 1.0854x; 1.0854x over previous
#include <cuda_runtime.h>
#include <cuda_fp16.h>
#include <math.h>
#include <stdint.h>
#include <stddef.h>

#define NB 8
#define LL 2048
#define NL (NB*LL)

// ---------------- device scratch (no allocations allowed) ----------------
static __device__ float4 g_qpack[NL];   // {qx,qy,qz, 0.5*|q|^2 * log2e}
static __device__ float4 g_ppack[NL];   // {px,py,pz, 0.5*|p|^2 * log2e}
static __device__ float  g_f[NL];
static __device__ float  g_g[NL];
static __device__ float  g_spart[4*NL]; // per-quarter row partial sums
static __device__ int    g_ctr[256];    // per-rowgroup arrival counters (zero-init)
static __device__ float  g_cnt[NB];
static __device__ float  g_loga[NB];
static __device__ float  g_cp[NB][3];
static __device__ float  g_ct[NB][3];
static __device__ float  g_R[NB][9];

#define L2E  1.4426950408889634f
#define LN2  0.6931471805599453f
#define E005M1 0.05127109637602412f   // exp(0.05)-1
#define E005   1.0512710963760241f    // exp(0.05)

__device__ __forceinline__ float ex2f_(float x){ float r; asm("ex2.approx.ftz.f32 %0,%1;" : "=f"(r) : "f"(x)); return r; }
__device__ __forceinline__ float lg2f_(float x){ float r; asm("lg2.approx.ftz.f32 %0,%1;" : "=f"(r) : "f"(x)); return r; }

// ---------------- prep ----------------
__global__ void k_zero(){ if (threadIdx.x < NB) g_cnt[threadIdx.x] = 0.f; }

__global__ void k_prep(const float* __restrict__ pred, const float* __restrict__ tru,
                       const float* __restrict__ mgen){
    int t = blockIdx.x*256 + threadIdx.x;   // 0..NL-1
    float px = pred[3*t+0], py = pred[3*t+1], pz = pred[3*t+2];
    float qx = tru [3*t+0], qy = tru [3*t+1], qz = tru [3*t+2];
    g_ppack[t] = make_float4(px,py,pz, 0.5f*(px*px+py*py+pz*pz)*L2E);
    g_qpack[t] = make_float4(qx,qy,qz, 0.5f*(qx*qx+qy*qy+qz*qz)*L2E);
    g_g[t] = 0.f;
    __shared__ float sred[256];
    sred[threadIdx.x] = (mgen[t] != 0.f) ? 1.f : 0.f;
    __syncthreads();
    for (int s = 128; s > 0; s >>= 1){
        if (threadIdx.x < s) sred[threadIdx.x] += sred[threadIdx.x+s];
        __syncthreads();
    }
    if (threadIdx.x == 0) atomicAdd(&g_cnt[blockIdx.x>>3], sred[0]);  // 8 blocks per batch
}

__global__ void k_prep2(){
    if (threadIdx.x < NB) g_loga[threadIdx.x] = -logf(fmaxf(g_cnt[threadIdx.x], 1.f));
}

// ---------------- sinkhorn half-update, f32 path (iterations 0-1) ----------------
__global__ void __launch_bounds__(256, 8) k_upd(int dir){
    __shared__ float4 tile[512];
    __shared__ float  part[64][9];
    __shared__ int    lastflag;

    const float4* colpack = dir ? g_ppack : g_qpack;
    const float*  colval  = dir ? g_f     : g_g;
    const float4* rowpack = dir ? g_qpack : g_ppack;
    float*        outv    = dir ? g_g     : g_f;

    int b   = blockIdx.x;
    int qtr = b & 3;                 // column quarter
    int rg  = b >> 2;                // rowgroup 0..255
    int n   = rg >> 5;               // 32 rowgroups per batch
    int row0 = (rg & 31) << 6;       // 64 rows per group
    int c0   = qtr << 9;             // 512 cols per quarter

    int tid = threadIdx.x, warp = tid >> 5, lane = tid & 31;

    const float4* cp = colpack + n*LL + c0;
    const float*  cv = colval  + n*LL + c0;
    #pragma unroll
    for (int i = tid; i < 512; i += 256){
        float4 c = cp[i];
        c.w = cv[i]*L2E - c.w;       // log2e*(val - 0.5|v|^2)
        tile[i] = c;
    }

    int r0 = row0 + lane, r1 = row0 + 32 + lane;
    float4 pa = rowpack[n*LL + r0];
    float4 pb = rowpack[n*LL + r1];
    float ax = pa.x*L2E, ay = pa.y*L2E, az = pa.z*L2E;
    float bx = pb.x*L2E, by = pb.y*L2E, bz = pb.z*L2E;

    __syncthreads();

    const float4* tp = tile + (warp << 6);       // 64 cols per warp
    float s00=0.f, s01=0.f, s10=0.f, s11=0.f;
    #pragma unroll 8
    for (int m = 0; m < 64; m += 2){
        float4 ca = tp[m], cb = tp[m+1];
        s00 += ex2f_(fmaf(ax,ca.x, fmaf(ay,ca.y, fmaf(az,ca.z, ca.w))));
        s10 += ex2f_(fmaf(bx,ca.x, fmaf(by,ca.y, fmaf(bz,ca.z, ca.w))));
        s01 += ex2f_(fmaf(ax,cb.x, fmaf(ay,cb.y, fmaf(az,cb.z, cb.w))));
        s11 += ex2f_(fmaf(bx,cb.x, fmaf(by,cb.y, fmaf(bz,cb.z, cb.w))));
    }
    part[lane][warp]    = s00 + s01;
    part[32+lane][warp] = s10 + s11;
    __syncthreads();

    if (warp < 2){
        int rr = (warp << 5) + lane;             // 0..63 row within group
        int r  = row0 + rr;                      // row within batch
        float S = 0.f;
        #pragma unroll
        for (int j = 0; j < 8; j++) S += part[rr][j];
        int cl = r - c0;
        if ((unsigned)cl < 512u){
            float4 cd = tile[cl];
            float dx = warp ? bx : ax;
            float dy = warp ? by : ay;
            float dz = warp ? bz : az;
            S += ex2f_(fmaf(dx, cd.x, fmaf(dy, cd.y, fmaf(dz, cd.z, cd.w)))) * E005M1;
        }
        __stcg(&g_spart[qtr*NL + n*LL + r], S);
    }
    __threadfence();
    __syncthreads();
    if (tid == 0){
        int old = atomicAdd(&g_ctr[rg], 1);
        lastflag = (old == 3);
    }
    __syncthreads();
    if (lastflag && warp < 2){
        int rr = (warp << 5) + lane;
        int gidx = n*LL + row0 + rr;
        float S = __ldcg(&g_spart[gidx])
                + __ldcg(&g_spart[NL   + gidx])
                + __ldcg(&g_spart[2*NL + gidx])
                + __ldcg(&g_spart[3*NL + gidx]);
        S = fmaxf(S, 1e-30f);
        float pw = rowpack[gidx].w;
        outv[gidx] = g_loga[n] + pw*LN2 - LN2*lg2f_(S);
        if (tid == 0) g_ctr[rg] = 0;
    }
}

// ---------------- sinkhorn half-update, f16x2 exp + HADD2 accumulate ----------
// Iterations 2-9. Centering c_grp (identical across the 4 quarter blocks of a
// rowgroup: computed from row data only) keeps args/sums in f16 range.
// Key fix vs R7: accumulate exps with HADD2 (fma pipe), unpack ONCE per thread
// -> MUFU carries only 2 ex2.f16x2 per 128 elems (vs 4 ex2.f32 in f32 path).
__global__ void __launch_bounds__(256) k_upd_h(int dir){
    __shared__ float4 tile[512];
    __shared__ float  part[64][9];
    __shared__ float  s_c;
    __shared__ int    lastflag;

    const float4* colpack = dir ? g_ppack : g_qpack;
    const float*  colval  = dir ? g_f     : g_g;
    const float4* rowpack = dir ? g_qpack : g_ppack;
    float*        outv    = dir ? g_g     : g_f;

    int b   = blockIdx.x;
    int qtr = b & 3;
    int rg  = b >> 2;
    int n   = rg >> 5;
    int row0 = (rg & 31) << 6;
    int c0   = qtr << 9;
    int tid = threadIdx.x, warp = tid >> 5, lane = tid & 31;

    int r0 = row0 + lane, r1 = row0 + 32 + lane;
    float4 pa = rowpack[n*LL + r0];
    float4 pb = rowpack[n*LL + r1];

    // group center from previous iterate (reads complete before this
    // iteration's finalizer can write these rows)
    if (warp == 0){
        float fpa = outv[n*LL + r0];
        float fpb = outv[n*LL + r1];
        float v = fmaxf(pa.w - fpa*L2E, pb.w - fpb*L2E);
        #pragma unroll
        for (int o = 16; o; o >>= 1) v = fmaxf(v, __shfl_xor_sync(0xFFFFFFFFu, v, o));
        if (lane == 0) s_c = g_loga[n]*L2E + v - 8.0f;
    }
    __syncthreads();
    float cgrp = s_c;

    const float4* cp = colpack + n*LL + c0;
    const float*  cv = colval  + n*LL + c0;
    #pragma unroll
    for (int i = tid; i < 512; i += 256){
        float4 c = cp[i];
        c.w = cv[i]*L2E - c.w - cgrp;   // centered log2-domain column term
        tile[i] = c;
    }

    float ax = pa.x*L2E, ay = pa.y*L2E, az = pa.z*L2E;
    float bx = pb.x*L2E, by = pb.y*L2E, bz = pb.z*L2E;
    __syncthreads();

    const float4* tp = tile + (warp << 6);
    __half2 accA0 = __half2(__float2half(0.f), __float2half(0.f));
    __half2 accA1 = accA0, accA2 = accA0, accA3 = accA0;
    __half2 accB0 = accA0, accB1 = accA0, accB2 = accA0, accB3 = accA0;
    #pragma unroll 4
    for (int m = 0; m < 64; m += 8){
        #pragma unroll
        for (int j = 0; j < 4; j++){
            float4 ca = tp[m + 2*j], cb = tp[m + 2*j + 1];
            float dA0 = fmaf(ax,ca.x, fmaf(ay,ca.y, fmaf(az,ca.z, ca.w)));
            float dA1 = fmaf(ax,cb.x, fmaf(ay,cb.y, fmaf(az,cb.z, cb.w)));
            float dB0 = fmaf(bx,ca.x, fmaf(by,ca.y, fmaf(bz,ca.z, ca.w)));
            float dB1 = fmaf(bx,cb.x, fmaf(by,cb.y, fmaf(bz,cb.z, cb.w)));
            unsigned uA, uB, eA, eB;
            asm("cvt.rn.f16x2.f32 %0, %1, %2;" : "=r"(uA) : "f"(dA0), "f"(dA1));
            asm("cvt.rn.f16x2.f32 %0, %1, %2;" : "=r"(uB) : "f"(dB0), "f"(dB1));
            asm("ex2.approx.f16x2 %0, %1;" : "=r"(eA) : "r"(uA));
            asm("ex2.approx.f16x2 %0, %1;" : "=r"(eB) : "r"(uB));
            __half2 hA = *reinterpret_cast<__half2*>(&eA);
            __half2 hB = *reinterpret_cast<__half2*>(&eB);
            if (j == 0){ accA0 = __hadd2(accA0, hA); accB0 = __hadd2(accB0, hB); }
            if (j == 1){ accA1 = __hadd2(accA1, hA); accB1 = __hadd2(accB1, hB); }
            if (j == 2){ accA2 = __hadd2(accA2, hA); accB2 = __hadd2(accB2, hB); }
            if (j == 3){ accA3 = __hadd2(accA3, hA); accB3 = __hadd2(accB3, hB); }
        }
    }
    // one unpack per thread: tree-add in f16x2, then 2 F2F per row
    __half2 tA = __hadd2(__hadd2(accA0, accA1), __hadd2(accA2, accA3));
    __half2 tB = __hadd2(__hadd2(accB0, accB1), __hadd2(accB2, accB3));
    float sA = __low2float(tA) + __high2float(tA);
    float sB = __low2float(tB) + __high2float(tB);
    part[lane][warp]    = sA;
    part[32+lane][warp] = sB;
    __syncthreads();

    if (warp < 2){
        int rr = (warp << 5) + lane;
        int r  = row0 + rr;
        float S = 0.f;
        #pragma unroll
        for (int j = 0; j < 8; j++) S += part[rr][j];
        // diagonal bias correction in f32 (tile.w already centered)
        int cl = r - c0;
        if ((unsigned)cl < 512u){
            float4 cd = tile[cl];
            float dx = warp ? bx : ax;
            float dy = warp ? by : ay;
            float dz = warp ? bz : az;
            S += ex2f_(fmaf(dx, cd.x, fmaf(dy, cd.y, fmaf(dz, cd.z, cd.w)))) * E005M1;
        }
        __stcg(&g_spart[qtr*NL + n*LL + r], S);
    }
    __threadfence();
    __syncthreads();
    if (tid == 0){
        int old = atomicAdd(&g_ctr[rg], 1);
        lastflag = (old == 3);
    }
    __syncthreads();
    if (lastflag && warp < 2){
        int rr = (warp << 5) + lane;
        int gidx = n*LL + row0 + rr;
        float S = __ldcg(&g_spart[gidx])
                + __ldcg(&g_spart[NL   + gidx])
                + __ldcg(&g_spart[2*NL + gidx])
                + __ldcg(&g_spart[3*NL + gidx]);
        S = fmaxf(S, 1e-30f);
        float pw = rowpack[gidx].w;
        // true ln(sum) = LN2*(cgrp + log2(S_centered))
        outv[gidx] = g_loga[n] + pw*LN2 - LN2*(cgrp + lg2f_(S));
        if (tid == 0) g_ctr[rg] = 0;
    }
}

// ---------------- pi + true_pos_mapped ----------------
__global__ void __launch_bounds__(512) k_pi(float* __restrict__ piout, float* __restrict__ tpmout){
    __shared__ float4 tile[LL];
    int n    = blockIdx.x >> 7;          // 128 blocks per batch (16 rows each)
    int row0 = (blockIdx.x & 127) << 4;
    int tid  = threadIdx.x;

    const float4* qp = g_qpack + n*LL;
    const float*  gg = g_g     + n*LL;
    for (int i = tid; i < LL; i += 512){
        float4 c = qp[i];
        c.w = gg[i]*L2E - c.w;
        tile[i] = c;
    }
    __syncthreads();

    int warp = tid >> 5, lane = tid & 31;
    int l = row0 + warp;
    float4 pp = g_ppack[n*LL + l];
    float fp2 = g_f[n*LL + l]*L2E - pp.w;
    float ppx = pp.x*L2E, ppy = pp.y*L2E, ppz = pp.z*L2E;

    float tx=0.f, ty=0.f, tz=0.f;
    float* po = piout + ((size_t)n*LL + l)*LL;
    #pragma unroll 4
    for (int m = lane; m < LL; m += 32){
        float4 c = tile[m];
        float pv = ex2f_(fp2 + fmaf(ppx,c.x, fmaf(ppy,c.y, fmaf(ppz,c.z, c.w))));
        if (m == l) pv *= E005;
        po[m] = pv;
        tx = fmaf(pv, c.x, tx);
        ty = fmaf(pv, c.y, ty);
        tz = fmaf(pv, c.z, tz);
    }
    #pragma unroll
    for (int o = 16; o; o >>= 1){
        tx += __shfl_xor_sync(0xFFFFFFFFu, tx, o);
        ty += __shfl_xor_sync(0xFFFFFFFFu, ty, o);
        tz += __shfl_xor_sync(0xFFFFFFFFu, tz, o);
    }
    if (lane == 0){
        float* tp = tpmout + (size_t)(n*LL + l)*3;
        tp[0] = tx; tp[1] = ty; tp[2] = tz;
    }
}

// ---------------- Kabsch + 3x3 SVD (per batch) ----------------
__global__ void k_kabsch(const float* __restrict__ pred, const float* __restrict__ tpm){
    int n = blockIdx.x, tid = threadIdx.x;
    float s[15];
    #pragma unroll
    for (int k = 0; k < 15; k++) s[k] = 0.f;
    for (int l = tid; l < LL; l += 256){
        const float* p = pred + (size_t)(n*LL + l)*3;
        const float* q = tpm  + (size_t)(n*LL + l)*3;
        float p0=p[0],p1=p[1],p2=p[2], q0=q[0],q1=q[1],q2=q[2];
        s[0]+=p0; s[1]+=p1; s[2]+=p2; s[3]+=q0; s[4]+=q1; s[5]+=q2;
        s[6]+=p0*q0;  s[7]+=p0*q1;  s[8]+=p0*q2;
        s[9]+=p1*q0;  s[10]+=p1*q1; s[11]+=p1*q2;
        s[12]+=p2*q0; s[13]+=p2*q1; s[14]+=p2*q2;
    }
    __shared__ float red[256];
    __shared__ float tot[15];
    for (int k = 0; k < 15; k++){
        red[tid] = s[k]; __syncthreads();
        for (int st = 128; st; st >>= 1){
            if (tid < st) red[tid] += red[tid+st];
            __syncthreads();
        }
        if (tid == 0) tot[k] = red[0];
        __syncthreads();
    }
    if (tid != 0) return;

    double w = fmax((double)g_cnt[n], 1e-6);
    double cp[3] = { tot[0]/w, tot[1]/w, tot[2]/w };
    double cq[3] = { tot[3]/w, tot[4]/w, tot[5]/w };
    double H[3][3];
    for (int i = 0; i < 3; i++)
        for (int j = 0; j < 3; j++)
            H[i][j] = (double)tot[6 + 3*i + j] - w*cp[i]*cq[j];

    double fn = 0.0;
    for (int i = 0; i < 3; i++) for (int j = 0; j < 3; j++) fn += H[i][j]*H[i][j];
    fn = fmax(sqrt(fn), 1e-8);
    double M[3][3];
    for (int i = 0; i < 3; i++)
        for (int j = 0; j < 3; j++)
            M[i][j] = H[i][j]/fn + (i==j ? 1e-4 : 0.0);

    double B[3][3];
    for (int i = 0; i < 3; i++)
        for (int j = 0; j < 3; j++){
            double acc = 0.0;
            for (int k = 0; k < 3; k++) acc += M[k][i]*M[k][j];
            B[i][j] = acc;
        }
    double V[3][3] = {{1,0,0},{0,1,0},{0,0,1}};
    for (int sw = 0; sw < 15; sw++){
        for (int pair = 0; pair < 3; pair++){
            int p = (pair==2) ? 1 : 0;
            int q = (pair==0) ? 1 : 2;
            double apq = B[p][q];
            if (fabs(apq) < 1e-30) continue;
            double tau = (B[q][q] - B[p][p])/(2.0*apq);
            double t = ((tau >= 0.0) ? 1.0 : -1.0)/(fabs(tau) + sqrt(1.0 + tau*tau));
            double c = 1.0/sqrt(1.0 + t*t), sn = t*c;
            for (int k = 0; k < 3; k++){
                double bkp = B[k][p], bkq = B[k][q];
                B[k][p] = c*bkp - sn*bkq; B[k][q] = sn*bkp + c*bkq;
            }
            for (int k = 0; k < 3; k++){
                double bpk = B[p][k], bqk = B[q][k];
                B[p][k] = c*bpk - sn*bqk; B[q][k] = sn*bpk + c*bqk;
            }
            for (int k = 0; k < 3; k++){
                double vkp = V[k][p], vkq = V[k][q];
                V[k][p] = c*vkp - sn*vkq; V[k][q] = sn*vkp + c*vkq;
            }
        }
    }
    double lam[3] = { B[0][0], B[1][1], B[2][2] };
    for (int i = 0; i < 2; i++)
        for (int j = 0; j < 2 - i; j++)
            if (lam[j] < lam[j+1]){
                double tl = lam[j]; lam[j] = lam[j+1]; lam[j+1] = tl;
                for (int k = 0; k < 3; k++){ double tv = V[k][j]; V[k][j] = V[k][j+1]; V[k][j+1] = tv; }
            }
    double detV = V[0][0]*(V[1][1]*V[2][2]-V[1][2]*V[2][1])
                - V[0][1]*(V[1][0]*V[2][2]-V[1][2]*V[2][0])
                + V[0][2]*(V[1][0]*V[2][1]-V[1][1]*V[2][0]);
    if (detV < 0.0) for (int k = 0; k < 3; k++) V[k][2] = -V[k][2];

    double s1 = sqrt(fmax(lam[0], 0.0)), s2 = sqrt(fmax(lam[1], 0.0));
    double u1[3], u2[3], u3[3];
    for (int k = 0; k < 3; k++){
        u1[k] = (M[k][0]*V[0][0] + M[k][1]*V[1][0] + M[k][2]*V[2][0]) / fmax(s1, 1e-30);
        u2[k] = (M[k][0]*V[0][1] + M[k][1]*V[1][1] + M[k][2]*V[2][1]) / fmax(s2, 1e-30);
    }
    double n1 = sqrt(u1[0]*u1[0]+u1[1]*u1[1]+u1[2]*u1[2]);
    for (int k = 0; k < 3; k++) u1[k] /= fmax(n1, 1e-30);
    double d12 = u1[0]*u2[0]+u1[1]*u2[1]+u1[2]*u2[2];
    for (int k = 0; k < 3; k++) u2[k] -= d12*u1[k];
    double n2 = sqrt(u2[0]*u2[0]+u2[1]*u2[1]+u2[2]*u2[2]);
    for (int k = 0; k < 3; k++) u2[k] /= fmax(n2, 1e-30);
    u3[0] = u1[1]*u2[2] - u1[2]*u2[1];
    u3[1] = u1[2]*u2[0] - u1[0]*u2[2];
    u3[2] = u1[0]*u2[1] - u1[1]*u2[0];

    for (int d = 0; d < 3; d++)
        for (int e = 0; e < 3; e++)
            g_R[n][3*d + e] = (float)(u1[d]*V[e][0] + u2[d]*V[e][1] + u3[d]*V[e][2]);
    for (int k = 0; k < 3; k++){ g_cp[n][k] = (float)cp[k]; g_ct[n][k] = (float)cq[k]; }
}

// ---------------- TM score ----------------
__global__ void k_tm(const float* __restrict__ pred, const float* __restrict__ mgen,
                     const float* __restrict__ tpm, float* __restrict__ avg, float inv_d02){
    int n = blockIdx.x, tid = threadIdx.x;
    float R[9];
    #pragma unroll
    for (int k = 0; k < 9; k++) R[k] = g_R[n][k];
    float cp0 = g_cp[n][0], cp1 = g_cp[n][1], cp2 = g_cp[n][2];
    float ct0 = g_ct[n][0], ct1 = g_ct[n][1], ct2 = g_ct[n][2];

    float st = 0.f, sm = 0.f;
    for (int l = tid; l < LL; l += 256){
        const float* p = pred + (size_t)(n*LL + l)*3;
        const float* q = tpm  + (size_t)(n*LL + l)*3;
        float x0 = p[0]-cp0, x1 = p[1]-cp1, x2 = p[2]-cp2;
        float a0 = x0*R[0] + x1*R[3] + x2*R[6] + ct0;
        float a1 = x0*R[1] + x1*R[4] + x2*R[7] + ct1;
        float a2 = x0*R[2] + x1*R[5] + x2*R[8] + ct2;
        float d0 = a0-q[0], d1 = a1-q[1], d2 = a2-q[2];
        float dsq = d0*d0 + d1*d1 + d2*d2;
        float tm = 1.f/(1.f + dsq*inv_d02);
        float mg = mgen[n*LL + l];
        st += tm*mg; sm += mg;
    }
    __shared__ float r1[256], r2[256];
    r1[tid] = st; r2[tid] = sm; __syncthreads();
    for (int s = 128; s; s >>= 1){
        if (tid < s){ r1[tid] += r1[tid+s]; r2[tid] += r2[tid+s]; }
        __syncthreads();
    }
    if (tid == 0) avg[n] = r1[0] / fmaxf(r2[0], 1e-6f);
}

// ---------------- launch ----------------
extern "C" void kernel_launch(void* const* d_in, const int* in_sizes, int n_in,
                              void* d_out, int out_size){
    const float* pred = (const float*)d_in[0];
    const float* tru  = (const float*)d_in[1];
    const float* mgen = (const float*)d_in[2];

    float* out   = (float*)d_out;
    float* avg   = out;                       // (N,)
    float* tpm   = out + NB;                  // (N,L,3)
    float* piout = out + NB + (size_t)NL*3;   // (N,L,L)

    k_zero<<<1, 32>>>();
    k_prep<<<NL/256, 256>>>(pred, tru, mgen);
    k_prep2<<<1, 32>>>();

    // iterations 0-1: f32 path (centering estimate not yet reliable)
    for (int it = 0; it < 2; it++){
        k_upd<<<1024, 256>>>(0);
        k_upd<<<1024, 256>>>(1);
    }
    // iterations 2-9: f16x2 exp + HADD2 accumulation (2x MUFU throughput)
    for (int it = 2; it < 10; it++){
        k_upd_h<<<1024, 256>>>(0);
        k_upd_h<<<1024, 256>>>(1);
    }

    k_pi<<<1024, 512>>>(piout, tpm);
    k_kabsch<<<NB, 256>>>(pred, tpm);

    double d0 = 1.24 * cbrt((double)((LL > 16 ? LL : 16) - 15)) - 1.8;
    if (d0 < 0.5) d0 = 0.5;
    float inv_d02 = (float)(1.0/(d0*d0));
    k_tm<<<NB, 256>>>(pred, mgen, tpm, avg, inv_d02);
}

// round 11
// speedup vs baseline: 1.1603x; 1.0690x over previous
#include <cuda_runtime.h>
#include <math.h>
#include <stdint.h>
#include <stddef.h>

#define NB 8
#define LL 2048
#define NL (NB*LL)
#define KROW (LL/2)   // u32 (bf16x2) per K row

// ---------------- device scratch (no allocations allowed) ----------------
static __device__ float4 g_qpack[NL];   // {qx,qy,qz, 0.5*|q|^2 * log2e}
static __device__ float4 g_ppack[NL];   // {px,py,pz, 0.5*|p|^2 * log2e}
static __device__ float  g_f[NL];
static __device__ float  g_g[NL];
static __device__ float  g_u[NL];       // exp(f)
static __device__ float  g_v[NL];       // exp(g)
static __device__ float  g_spart[4*NL]; // cross-block partial sums
static __device__ int    g_ctr[256];    // arrival counters (f-update)
static __device__ int    g_ctr2[256];   // arrival counters (g-update)
static __device__ float  g_cnt[NB];
static __device__ float  g_ab[NB];      // a = b = 1/count
static __device__ float  g_cp[NB][3];
static __device__ float  g_ct[NB][3];
static __device__ float  g_R[NB][9];
// Gibbs kernel K = exp(-M) in bf16 pairs, row-major. 67 MB.
static __device__ unsigned int g_K[(size_t)NB * LL * KROW];

#define L2E  1.4426950408889634f
#define LN2  0.6931471805599453f
#define E005 1.0512710963760241f    // exp(0.05) (diag bias: cost -0.1 => M -0.05)

__device__ __forceinline__ float ex2f_(float x){ float r; asm("ex2.approx.ftz.f32 %0,%1;" : "=f"(r) : "f"(x)); return r; }
__device__ __forceinline__ float lg2f_(float x){ float r; asm("lg2.approx.ftz.f32 %0,%1;" : "=f"(r) : "f"(x)); return r; }
__device__ __forceinline__ float bflo(unsigned int k){ return __uint_as_float(k << 16); }
__device__ __forceinline__ float bfhi(unsigned int k){ return __uint_as_float(k & 0xffff0000u); }

// ---------------- prep ----------------
__global__ void k_zero(){ if (threadIdx.x < NB) g_cnt[threadIdx.x] = 0.f; }

__global__ void k_prep(const float* __restrict__ pred, const float* __restrict__ tru,
                       const float* __restrict__ mgen){
    int t = blockIdx.x*256 + threadIdx.x;   // 0..NL-1
    float px = pred[3*t+0], py = pred[3*t+1], pz = pred[3*t+2];
    float qx = tru [3*t+0], qy = tru [3*t+1], qz = tru [3*t+2];
    g_ppack[t] = make_float4(px,py,pz, 0.5f*(px*px+py*py+pz*pz)*L2E);
    g_qpack[t] = make_float4(qx,qy,qz, 0.5f*(qx*qx+qy*qy+qz*qz)*L2E);
    g_v[t] = 1.0f;                          // v = exp(g), g starts at 0
    __shared__ float sred[256];
    sred[threadIdx.x] = (mgen[t] != 0.f) ? 1.f : 0.f;
    __syncthreads();
    for (int s = 128; s > 0; s >>= 1){
        if (threadIdx.x < s) sred[threadIdx.x] += sred[threadIdx.x+s];
        __syncthreads();
    }
    if (threadIdx.x == 0) atomicAdd(&g_cnt[blockIdx.x>>3], sred[0]);  // 8 blocks per batch
}

__global__ void k_prep2(){
    if (threadIdx.x < NB) g_ab[threadIdx.x] = 1.0f / fmaxf(g_cnt[threadIdx.x], 1.f);
}

// ---------------- build K = exp(-M) once (bf16, row-major) ----------------
// block: 64 rows x 512 cols. warp = row; lane = col pair. MUFU-bound (~15us).
__global__ void __launch_bounds__(256) k_exp(){
    __shared__ float4 tile[512];
    int b = blockIdx.x;
    int qtr = b & 3, rg = b >> 2, n = rg >> 5;
    int row0 = (rg & 31) << 6, c0 = qtr << 9;
    int tid = threadIdx.x, w = tid >> 5, lane = tid & 31;

    for (int i = tid; i < 512; i += 256) tile[i] = g_qpack[n*LL + c0 + i];
    __syncthreads();

    for (int i = 0; i < 8; i++){
        int r = row0 + w + 8*i;
        float4 pp = g_ppack[n*LL + r];
        float px = pp.x*L2E, py = pp.y*L2E, pz = pp.z*L2E, pw = pp.w;
        unsigned int* dst = g_K + ((size_t)n*LL + r)*KROW + (c0 >> 1);
        #pragma unroll
        for (int j = 0; j < 8; j++){
            int p = lane + 32*j;             // pair index within 512-col strip
            float4 t0 = tile[2*p], t1 = tile[2*p+1];
            // arg = log2e*(p.q - |p|^2/2 - |q|^2/2) = -M*log2e
            float a0 = fmaf(px,t0.x, fmaf(py,t0.y, fmaf(pz,t0.z, -(pw + t0.w))));
            float a1 = fmaf(px,t1.x, fmaf(py,t1.y, fmaf(pz,t1.z, -(pw + t1.w))));
            float e0 = ex2f_(a0), e1 = ex2f_(a1);
            int gc = c0 + 2*p;
            if (gc     == r) e0 *= E005;     // diag bias folded into K
            if (gc + 1 == r) e1 *= E005;
            unsigned int kk;
            asm("cvt.rn.bf16x2.f32 %0, %1, %2;" : "=r"(kk) : "f"(e1), "f"(e0));
            dst[p] = kk;                     // low half = col gc, high = gc+1
        }
    }
}

// ---------------- f half-update: u = a / (K v)  (row-parallel) ----------------
// block: 64 rows x 512 cols; 4 column-quarters combined via g_spart + g_ctr.
__global__ void __launch_bounds__(256) k_mvf(){
    __shared__ float4 vsm[128];              // 512 v values
    __shared__ int lastflag;
    int b = blockIdx.x;
    int qtr = b & 3, rg = b >> 2, n = rg >> 5;
    int row0 = (rg & 31) << 6, c0 = qtr << 9;
    int tid = threadIdx.x, w = tid >> 5, lane = tid & 31;

    float* vf = (float*)vsm;
    for (int i = tid; i < 512; i += 256) vf[i] = g_v[n*LL + c0 + i];
    __syncthreads();

    for (int i = 0; i < 8; i++){
        int r = row0 + w + 8*i;
        const uint2* Kr = (const uint2*)(g_K + ((size_t)n*LL + r)*KROW + (c0 >> 1));
        float acc = 0.f;
        #pragma unroll
        for (int s = 0; s < 4; s++){
            int e = lane + 32*s;             // uint2 = 4 cols; matches vsm[e]
            uint2 kk = Kr[e];
            float4 vv = vsm[e];
            acc = fmaf(bflo(kk.x), vv.x,
                  fmaf(bfhi(kk.x), vv.y,
                  fmaf(bflo(kk.y), vv.z,
                  fmaf(bfhi(kk.y), vv.w, acc))));
        }
        #pragma unroll
        for (int o = 16; o; o >>= 1) acc += __shfl_xor_sync(0xFFFFFFFFu, acc, o);
        if (lane == 0) __stcg(&g_spart[qtr*NL + n*LL + r], acc);
    }
    __threadfence();
    __syncthreads();
    if (tid == 0) lastflag = (atomicAdd(&g_ctr[rg], 1) == 3);
    __syncthreads();
    if (lastflag && w < 2){
        int rr = (w << 5) + lane;
        int gidx = n*LL + row0 + rr;
        float S = __ldcg(&g_spart[gidx])
                + __ldcg(&g_spart[NL   + gidx])
                + __ldcg(&g_spart[2*NL + gidx])
                + __ldcg(&g_spart[3*NL + gidx]);
        g_u[gidx] = __fdividef(g_ab[n], fmaxf(S, 1e-35f));
        if (tid == 0) g_ctr[rg] = 0;
    }
}

// ---------------- g half-update: v = b / (K^T u)  (column-in-register) ------
// block: 512 rows x 64 cols; 4 row-quarters combined via g_spart + g_ctr2.
// K read row-major coalesced (128B per warp-row-step); u broadcast from smem.
__global__ void __launch_bounds__(256) k_mvg(){
    __shared__ float usm[512];
    __shared__ float psum[8][64];
    __shared__ int lastflag;
    int b = blockIdx.x;
    int n = b >> 7, strip = (b >> 2) & 31, rq = b & 3;
    int r0 = rq << 9, c0 = strip << 6;
    int tid = threadIdx.x, cp = tid & 31, rs = tid >> 5;

    for (int i = tid; i < 512; i += 256) usm[i] = g_u[n*LL + r0 + i];
    __syncthreads();

    const unsigned int* Kc = g_K + ((size_t)n*LL + r0)*KROW + (c0 >> 1) + cp;
    float t0 = 0.f, t1 = 0.f;
    #pragma unroll 4
    for (int i = 0; i < 64; i++){
        int lr = rs + 8*i;
        unsigned int kk = Kc[(size_t)lr * KROW];
        float ur = usm[lr];
        t0 = fmaf(bflo(kk), ur, t0);
        t1 = fmaf(bfhi(kk), ur, t1);
    }
    psum[rs][2*cp]   = t0;
    psum[rs][2*cp+1] = t1;
    __syncthreads();
    if (tid < 64){
        float T = 0.f;
        #pragma unroll
        for (int j = 0; j < 8; j++) T += psum[j][tid];
        __stcg(&g_spart[rq*NL + n*LL + c0 + tid], T);
    }
    __threadfence();
    __syncthreads();
    if (tid == 0) lastflag = (atomicAdd(&g_ctr2[n*32 + strip], 1) == 3);
    __syncthreads();
    if (lastflag && tid < 64){
        int gidx = n*LL + c0 + tid;
        float T = __ldcg(&g_spart[gidx])
                + __ldcg(&g_spart[NL   + gidx])
                + __ldcg(&g_spart[2*NL + gidx])
                + __ldcg(&g_spart[3*NL + gidx]);
        g_v[gidx] = __fdividef(g_ab[n], fmaxf(T, 1e-35f));
        if (tid == 0) g_ctr2[n*32 + strip] = 0;
    }
}

// ---------------- convert u,v -> f,g for the pi kernel ----------------
__global__ void k_fg(){
    int t = blockIdx.x*256 + threadIdx.x;
    g_f[t] = LN2 * lg2f_(g_u[t]);
    g_g[t] = LN2 * lg2f_(g_v[t]);
}

// ---------------- pi + true_pos_mapped (full f32 precision) ----------------
__global__ void __launch_bounds__(512) k_pi(float* __restrict__ piout, float* __restrict__ tpmout){
    __shared__ float4 tile[LL];
    int n    = blockIdx.x >> 7;          // 128 blocks per batch (16 rows each)
    int row0 = (blockIdx.x & 127) << 4;
    int tid  = threadIdx.x;

    const float4* qp = g_qpack + n*LL;
    const float*  gg = g_g     + n*LL;
    for (int i = tid; i < LL; i += 512){
        float4 c = qp[i];
        c.w = gg[i]*L2E - c.w;
        tile[i] = c;
    }
    __syncthreads();

    int warp = tid >> 5, lane = tid & 31;
    int l = row0 + warp;
    float4 pp = g_ppack[n*LL + l];
    float fp2 = g_f[n*LL + l]*L2E - pp.w;
    float ppx = pp.x*L2E, ppy = pp.y*L2E, ppz = pp.z*L2E;

    float tx=0.f, ty=0.f, tz=0.f;
    float* po = piout + ((size_t)n*LL + l)*LL;
    #pragma unroll 4
    for (int m = lane; m < LL; m += 32){
        float4 c = tile[m];
        float pv = ex2f_(fp2 + fmaf(ppx,c.x, fmaf(ppy,c.y, fmaf(ppz,c.z, c.w))));
        if (m == l) pv *= E005;
        po[m] = pv;
        tx = fmaf(pv, c.x, tx);
        ty = fmaf(pv, c.y, ty);
        tz = fmaf(pv, c.z, tz);
    }
    #pragma unroll
    for (int o = 16; o; o >>= 1){
        tx += __shfl_xor_sync(0xFFFFFFFFu, tx, o);
        ty += __shfl_xor_sync(0xFFFFFFFFu, ty, o);
        tz += __shfl_xor_sync(0xFFFFFFFFu, tz, o);
    }
    if (lane == 0){
        float* tp = tpmout + (size_t)(n*LL + l)*3;
        tp[0] = tx; tp[1] = ty; tp[2] = tz;
    }
}

// ---------------- Kabsch + 3x3 SVD (per batch) ----------------
__global__ void k_kabsch(const float* __restrict__ pred, const float* __restrict__ tpm){
    int n = blockIdx.x, tid = threadIdx.x;
    float s[15];
    #pragma unroll
    for (int k = 0; k < 15; k++) s[k] = 0.f;
    for (int l = tid; l < LL; l += 256){
        const float* p = pred + (size_t)(n*LL + l)*3;
        const float* q = tpm  + (size_t)(n*LL + l)*3;
        float p0=p[0],p1=p[1],p2=p[2], q0=q[0],q1=q[1],q2=q[2];
        s[0]+=p0; s[1]+=p1; s[2]+=p2; s[3]+=q0; s[4]+=q1; s[5]+=q2;
        s[6]+=p0*q0;  s[7]+=p0*q1;  s[8]+=p0*q2;
        s[9]+=p1*q0;  s[10]+=p1*q1; s[11]+=p1*q2;
        s[12]+=p2*q0; s[13]+=p2*q1; s[14]+=p2*q2;
    }
    __shared__ float red[256];
    __shared__ float tot[15];
    for (int k = 0; k < 15; k++){
        red[tid] = s[k]; __syncthreads();
        for (int st = 128; st; st >>= 1){
            if (tid < st) red[tid] += red[tid+st];
            __syncthreads();
        }
        if (tid == 0) tot[k] = red[0];
        __syncthreads();
    }
    if (tid != 0) return;

    double w = fmax((double)g_cnt[n], 1e-6);
    double cp[3] = { tot[0]/w, tot[1]/w, tot[2]/w };
    double cq[3] = { tot[3]/w, tot[4]/w, tot[5]/w };
    double H[3][3];
    for (int i = 0; i < 3; i++)
        for (int j = 0; j < 3; j++)
            H[i][j] = (double)tot[6 + 3*i + j] - w*cp[i]*cq[j];

    double fn = 0.0;
    for (int i = 0; i < 3; i++) for (int j = 0; j < 3; j++) fn += H[i][j]*H[i][j];
    fn = fmax(sqrt(fn), 1e-8);
    double M[3][3];
    for (int i = 0; i < 3; i++)
        for (int j = 0; j < 3; j++)
            M[i][j] = H[i][j]/fn + (i==j ? 1e-4 : 0.0);

    double B[3][3];
    for (int i = 0; i < 3; i++)
        for (int j = 0; j < 3; j++){
            double acc = 0.0;
            for (int k = 0; k < 3; k++) acc += M[k][i]*M[k][j];
            B[i][j] = acc;
        }
    double V[3][3] = {{1,0,0},{0,1,0},{0,0,1}};
    for (int sw = 0; sw < 15; sw++){
        for (int pair = 0; pair < 3; pair++){
            int p = (pair==2) ? 1 : 0;
            int q = (pair==0) ? 1 : 2;
            double apq = B[p][q];
            if (fabs(apq) < 1e-30) continue;
            double tau = (B[q][q] - B[p][p])/(2.0*apq);
            double t = ((tau >= 0.0) ? 1.0 : -1.0)/(fabs(tau) + sqrt(1.0 + tau*tau));
            double c = 1.0/sqrt(1.0 + t*t), sn = t*c;
            for (int k = 0; k < 3; k++){
                double bkp = B[k][p], bkq = B[k][q];
                B[k][p] = c*bkp - sn*bkq; B[k][q] = sn*bkp + c*bkq;
            }
            for (int k = 0; k < 3; k++){
                double bpk = B[p][k], bqk = B[q][k];
                B[p][k] = c*bpk - sn*bqk; B[q][k] = sn*bpk + c*bqk;
            }
            for (int k = 0; k < 3; k++){
                double vkp = V[k][p], vkq = V[k][q];
                V[k][p] = c*vkp - sn*vkq; V[k][q] = sn*vkp + c*vkq;
            }
        }
    }
    double lam[3] = { B[0][0], B[1][1], B[2][2] };
    for (int i = 0; i < 2; i++)
        for (int j = 0; j < 2 - i; j++)
            if (lam[j] < lam[j+1]){
                double tl = lam[j]; lam[j] = lam[j+1]; lam[j+1] = tl;
                for (int k = 0; k < 3; k++){ double tv = V[k][j]; V[k][j] = V[k][j+1]; V[k][j+1] = tv; }
            }
    double detV = V[0][0]*(V[1][1]*V[2][2]-V[1][2]*V[2][1])
                - V[0][1]*(V[1][0]*V[2][2]-V[1][2]*V[2][0])
                + V[0][2]*(V[1][0]*V[2][1]-V[1][1]*V[2][0]);
    if (detV < 0.0) for (int k = 0; k < 3; k++) V[k][2] = -V[k][2];

    double s1 = sqrt(fmax(lam[0], 0.0)), s2 = sqrt(fmax(lam[1], 0.0));
    double u1[3], u2[3], u3[3];
    for (int k = 0; k < 3; k++){
        u1[k] = (M[k][0]*V[0][0] + M[k][1]*V[1][0] + M[k][2]*V[2][0]) / fmax(s1, 1e-30);
        u2[k] = (M[k][0]*V[0][1] + M[k][1]*V[1][1] + M[k][2]*V[2][1]) / fmax(s2, 1e-30);
    }
    double n1 = sqrt(u1[0]*u1[0]+u1[1]*u1[1]+u1[2]*u1[2]);
    for (int k = 0; k < 3; k++) u1[k] /= fmax(n1, 1e-30);
    double d12 = u1[0]*u2[0]+u1[1]*u2[1]+u1[2]*u2[2];
    for (int k = 0; k < 3; k++) u2[k] -= d12*u1[k];
    double n2 = sqrt(u2[0]*u2[0]+u2[1]*u2[1]+u2[2]*u2[2]);
    for (int k = 0; k < 3; k++) u2[k] /= fmax(n2, 1e-30);
    u3[0] = u1[1]*u2[2] - u1[2]*u2[1];
    u3[1] = u1[2]*u2[0] - u1[0]*u2[2];
    u3[2] = u1[0]*u2[1] - u1[1]*u2[0];

    for (int d = 0; d < 3; d++)
        for (int e = 0; e < 3; e++)
            g_R[n][3*d + e] = (float)(u1[d]*V[e][0] + u2[d]*V[e][1] + u3[d]*V[e][2]);
    for (int k = 0; k < 3; k++){ g_cp[n][k] = (float)cp[k]; g_ct[n][k] = (float)cq[k]; }
}

// ---------------- TM score ----------------
__global__ void k_tm(const float* __restrict__ pred, const float* __restrict__ mgen,
                     const float* __restrict__ tpm, float* __restrict__ avg, float inv_d02){
    int n = blockIdx.x, tid = threadIdx.x;
    float R[9];
    #pragma unroll
    for (int k = 0; k < 9; k++) R[k] = g_R[n][k];
    float cp0 = g_cp[n][0], cp1 = g_cp[n][1], cp2 = g_cp[n][2];
    float ct0 = g_ct[n][0], ct1 = g_ct[n][1], ct2 = g_ct[n][2];

    float st = 0.f, sm = 0.f;
    for (int l = tid; l < LL; l += 256){
        const float* p = pred + (size_t)(n*LL + l)*3;
        const float* q = tpm  + (size_t)(n*LL + l)*3;
        float x0 = p[0]-cp0, x1 = p[1]-cp1, x2 = p[2]-cp2;
        float a0 = x0*R[0] + x1*R[3] + x2*R[6] + ct0;
        float a1 = x0*R[1] + x1*R[4] + x2*R[7] + ct1;
        float a2 = x0*R[2] + x1*R[5] + x2*R[8] + ct2;
        float d0 = a0-q[0], d1 = a1-q[1], d2 = a2-q[2];
        float dsq = d0*d0 + d1*d1 + d2*d2;
        float tm = 1.f/(1.f + dsq*inv_d02);
        float mg = mgen[n*LL + l];
        st += tm*mg; sm += mg;
    }
    __shared__ float r1[256], r2[256];
    r1[tid] = st; r2[tid] = sm; __syncthreads();
    for (int s = 128; s; s >>= 1){
        if (tid < s){ r1[tid] += r1[tid+s]; r2[tid] += r2[tid+s]; }
        __syncthreads();
    }
    if (tid == 0) avg[n] = r1[0] / fmaxf(r2[0], 1e-6f);
}

// ---------------- launch ----------------
extern "C" void kernel_launch(void* const* d_in, const int* in_sizes, int n_in,
                              void* d_out, int out_size){
    const float* pred = (const float*)d_in[0];
    const float* tru  = (const float*)d_in[1];
    const float* mgen = (const float*)d_in[2];

    float* out   = (float*)d_out;
    float* avg   = out;                       // (N,)
    float* tpm   = out + NB;                  // (N,L,3)
    float* piout = out + NB + (size_t)NL*3;   // (N,L,L)

    k_zero<<<1, 32>>>();
    k_prep<<<NL/256, 256>>>(pred, tru, mgen);
    k_prep2<<<1, 32>>>();

    k_exp<<<1024, 256>>>();                   // build K once (only exp-heavy pass)

    for (int it = 0; it < 10; it++){
        k_mvf<<<1024, 256>>>();               // u = a / (K v)
        k_mvg<<<1024, 256>>>();               // v = b / (K^T u)
    }

    k_fg<<<NL/256, 256>>>();
    k_pi<<<1024, 512>>>(piout, tpm);
    k_kabsch<<<NB, 256>>>(pred, tpm);

    double d0 = 1.24 * cbrt((double)((LL > 16 ? LL : 16) - 15)) - 1.8;
    if (d0 < 0.5) d0 = 0.5;
    float inv_d02 = (float)(1.0/(d0*d0));
    k_tm<<<NB, 256>>>(pred, mgen, tpm, avg, inv_d02);
}

// round 12
// speedup vs baseline: 1.1608x; 1.0004x over previous
#include <cuda_runtime.h>
#include <math.h>
#include <stdint.h>
#include <stddef.h>

#define NB 8
#define LL 2048
#define NL (NB*LL)
#define KROW (LL/2)   // u32 (bf16x2) per K row

// ---------------- device scratch (no allocations allowed) ----------------
static __device__ float4 g_qpack[NL];   // {qx,qy,qz, 0.5*|q|^2 * log2e}
static __device__ float4 g_ppack[NL];   // {px,py,pz, 0.5*|p|^2 * log2e}
static __device__ float  g_f[NL];
static __device__ float  g_g[NL];
static __device__ float  g_u[NL];       // exp(f)
static __device__ float  g_v[NL];       // exp(g)
static __device__ float  g_spart[4*NL]; // cross-block partial sums
static __device__ int    g_ctr[256];    // arrival counters (f-update)
static __device__ int    g_ctr2[256];   // arrival counters (g-update)
static __device__ float  g_cnt[NB];
static __device__ float  g_ab[NB];      // a = b = 1/count
static __device__ float  g_cp[NB][3];
static __device__ float  g_ct[NB][3];
static __device__ float  g_R[NB][9];
// Gibbs kernel K = exp(-M) in bf16 pairs, row-major. 67 MB.
static __device__ unsigned int g_K[(size_t)NB * LL * KROW];

#define L2E  1.4426950408889634f
#define LN2  0.6931471805599453f
#define E005 1.0512710963760241f    // exp(0.05) (diag bias: cost -0.1 => M -0.05)

__device__ __forceinline__ float ex2f_(float x){ float r; asm("ex2.approx.ftz.f32 %0,%1;" : "=f"(r) : "f"(x)); return r; }
__device__ __forceinline__ float lg2f_(float x){ float r; asm("lg2.approx.ftz.f32 %0,%1;" : "=f"(r) : "f"(x)); return r; }
__device__ __forceinline__ float bflo(unsigned int k){ return __uint_as_float(k << 16); }
__device__ __forceinline__ float bfhi(unsigned int k){ return __uint_as_float(k & 0xffff0000u); }

// ---------------- prep ----------------
__global__ void k_zero(){ if (threadIdx.x < NB) g_cnt[threadIdx.x] = 0.f; }

__global__ void k_prep(const float* __restrict__ pred, const float* __restrict__ tru,
                       const float* __restrict__ mgen){
    int t = blockIdx.x*256 + threadIdx.x;   // 0..NL-1
    float px = pred[3*t+0], py = pred[3*t+1], pz = pred[3*t+2];
    float qx = tru [3*t+0], qy = tru [3*t+1], qz = tru [3*t+2];
    g_ppack[t] = make_float4(px,py,pz, 0.5f*(px*px+py*py+pz*pz)*L2E);
    g_qpack[t] = make_float4(qx,qy,qz, 0.5f*(qx*qx+qy*qy+qz*qz)*L2E);
    g_v[t] = 1.0f;                          // v = exp(g), g starts at 0
    __shared__ float sred[256];
    sred[threadIdx.x] = (mgen[t] != 0.f) ? 1.f : 0.f;
    __syncthreads();
    for (int s = 128; s > 0; s >>= 1){
        if (threadIdx.x < s) sred[threadIdx.x] += sred[threadIdx.x+s];
        __syncthreads();
    }
    if (threadIdx.x == 0) atomicAdd(&g_cnt[blockIdx.x>>3], sred[0]);  // 8 blocks per batch
}

__global__ void k_prep2(){
    if (threadIdx.x < NB) g_ab[threadIdx.x] = 1.0f / fmaxf(g_cnt[threadIdx.x], 1.f);
}

// ---------------- build K = exp(-M) once (bf16, row-major) ----------------
// block: 64 rows x 512 cols. warp = row; lane = col pair. MUFU-bound (~15us).
__global__ void __launch_bounds__(256) k_exp(){
    __shared__ float4 tile[512];
    int b = blockIdx.x;
    int qtr = b & 3, rg = b >> 2, n = rg >> 5;
    int row0 = (rg & 31) << 6, c0 = qtr << 9;
    int tid = threadIdx.x, w = tid >> 5, lane = tid & 31;

    for (int i = tid; i < 512; i += 256) tile[i] = g_qpack[n*LL + c0 + i];
    __syncthreads();

    for (int i = 0; i < 8; i++){
        int r = row0 + w + 8*i;
        float4 pp = g_ppack[n*LL + r];
        float px = pp.x*L2E, py = pp.y*L2E, pz = pp.z*L2E, pw = pp.w;
        unsigned int* dst = g_K + ((size_t)n*LL + r)*KROW + (c0 >> 1);
        #pragma unroll
        for (int j = 0; j < 8; j++){
            int p = lane + 32*j;             // pair index within 512-col strip
            float4 t0 = tile[2*p], t1 = tile[2*p+1];
            // arg = log2e*(p.q - |p|^2/2 - |q|^2/2) = -M*log2e
            float a0 = fmaf(px,t0.x, fmaf(py,t0.y, fmaf(pz,t0.z, -(pw + t0.w))));
            float a1 = fmaf(px,t1.x, fmaf(py,t1.y, fmaf(pz,t1.z, -(pw + t1.w))));
            float e0 = ex2f_(a0), e1 = ex2f_(a1);
            int gc = c0 + 2*p;
            if (gc     == r) e0 *= E005;     // diag bias folded into K
            if (gc + 1 == r) e1 *= E005;
            unsigned int kk;
            asm("cvt.rn.bf16x2.f32 %0, %1, %2;" : "=r"(kk) : "f"(e1), "f"(e0));
            dst[p] = kk;                     // low half = col gc, high = gc+1
        }
    }
}

// ---------------- f half-update: u = a / (K v)  (row-parallel) ----------------
// block: 64 rows x 512 cols; 4 column-quarters combined via g_spart + g_ctr.
__global__ void __launch_bounds__(256) k_mvf(){
    __shared__ float4 vsm[128];              // 512 v values
    __shared__ int lastflag;
    int b = blockIdx.x;
    int qtr = b & 3, rg = b >> 2, n = rg >> 5;
    int row0 = (rg & 31) << 6, c0 = qtr << 9;
    int tid = threadIdx.x, w = tid >> 5, lane = tid & 31;

    float* vf = (float*)vsm;
    for (int i = tid; i < 512; i += 256) vf[i] = g_v[n*LL + c0 + i];
    __syncthreads();

    for (int i = 0; i < 8; i++){
        int r = row0 + w + 8*i;
        const uint2* Kr = (const uint2*)(g_K + ((size_t)n*LL + r)*KROW + (c0 >> 1));
        float acc = 0.f;
        #pragma unroll
        for (int s = 0; s < 4; s++){
            int e = lane + 32*s;             // uint2 = 4 cols; matches vsm[e]
            uint2 kk = Kr[e];
            float4 vv = vsm[e];
            acc = fmaf(bflo(kk.x), vv.x,
                  fmaf(bfhi(kk.x), vv.y,
                  fmaf(bflo(kk.y), vv.z,
                  fmaf(bfhi(kk.y), vv.w, acc))));
        }
        #pragma unroll
        for (int o = 16; o; o >>= 1) acc += __shfl_xor_sync(0xFFFFFFFFu, acc, o);
        if (lane == 0) __stcg(&g_spart[qtr*NL + n*LL + r], acc);
    }
    __threadfence();
    __syncthreads();
    if (tid == 0) lastflag = (atomicAdd(&g_ctr[rg], 1) == 3);
    __syncthreads();
    if (lastflag && w < 2){
        int rr = (w << 5) + lane;
        int gidx = n*LL + row0 + rr;
        float S = __ldcg(&g_spart[gidx])
                + __ldcg(&g_spart[NL   + gidx])
                + __ldcg(&g_spart[2*NL + gidx])
                + __ldcg(&g_spart[3*NL + gidx]);
        g_u[gidx] = __fdividef(g_ab[n], fmaxf(S, 1e-35f));
        if (tid == 0) g_ctr[rg] = 0;
    }
}

// ---------------- g half-update: v = b / (K^T u)  (column-in-register) ------
// block: 512 rows x 64 cols; 4 row-quarters combined via g_spart + g_ctr2.
// K read row-major coalesced (128B per warp-row-step); u broadcast from smem.
__global__ void __launch_bounds__(256) k_mvg(){
    __shared__ float usm[512];
    __shared__ float psum[8][64];
    __shared__ int lastflag;
    int b = blockIdx.x;
    int n = b >> 7, strip = (b >> 2) & 31, rq = b & 3;
    int r0 = rq << 9, c0 = strip << 6;
    int tid = threadIdx.x, cp = tid & 31, rs = tid >> 5;

    for (int i = tid; i < 512; i += 256) usm[i] = g_u[n*LL + r0 + i];
    __syncthreads();

    const unsigned int* Kc = g_K + ((size_t)n*LL + r0)*KROW + (c0 >> 1) + cp;
    float t0 = 0.f, t1 = 0.f;
    #pragma unroll 4
    for (int i = 0; i < 64; i++){
        int lr = rs + 8*i;
        unsigned int kk = Kc[(size_t)lr * KROW];
        float ur = usm[lr];
        t0 = fmaf(bflo(kk), ur, t0);
        t1 = fmaf(bfhi(kk), ur, t1);
    }
    psum[rs][2*cp]   = t0;
    psum[rs][2*cp+1] = t1;
    __syncthreads();
    if (tid < 64){
        float T = 0.f;
        #pragma unroll
        for (int j = 0; j < 8; j++) T += psum[j][tid];
        __stcg(&g_spart[rq*NL + n*LL + c0 + tid], T);
    }
    __threadfence();
    __syncthreads();
    if (tid == 0) lastflag = (atomicAdd(&g_ctr2[n*32 + strip], 1) == 3);
    __syncthreads();
    if (lastflag && tid < 64){
        int gidx = n*LL + c0 + tid;
        float T = __ldcg(&g_spart[gidx])
                + __ldcg(&g_spart[NL   + gidx])
                + __ldcg(&g_spart[2*NL + gidx])
                + __ldcg(&g_spart[3*NL + gidx]);
        g_v[gidx] = __fdividef(g_ab[n], fmaxf(T, 1e-35f));
        if (tid == 0) g_ctr2[n*32 + strip] = 0;
    }
}

// ---------------- convert u,v -> f,g for the pi kernel ----------------
__global__ void k_fg(){
    int t = blockIdx.x*256 + threadIdx.x;
    g_f[t] = LN2 * lg2f_(g_u[t]);
    g_g[t] = LN2 * lg2f_(g_v[t]);
}

// ---------------- pi + true_pos_mapped (full f32 precision) ----------------
__global__ void __launch_bounds__(512) k_pi(float* __restrict__ piout, float* __restrict__ tpmout){
    __shared__ float4 tile[LL];
    int n    = blockIdx.x >> 7;          // 128 blocks per batch (16 rows each)
    int row0 = (blockIdx.x & 127) << 4;
    int tid  = threadIdx.x;

    const float4* qp = g_qpack + n*LL;
    const float*  gg = g_g     + n*LL;
    for (int i = tid; i < LL; i += 512){
        float4 c = qp[i];
        c.w = gg[i]*L2E - c.w;
        tile[i] = c;
    }
    __syncthreads();

    int warp = tid >> 5, lane = tid & 31;
    int l = row0 + warp;
    float4 pp = g_ppack[n*LL + l];
    float fp2 = g_f[n*LL + l]*L2E - pp.w;
    float ppx = pp.x*L2E, ppy = pp.y*L2E, ppz = pp.z*L2E;

    float tx=0.f, ty=0.f, tz=0.f;
    float* po = piout + ((size_t)n*LL + l)*LL;
    #pragma unroll 4
    for (int m = lane; m < LL; m += 32){
        float4 c = tile[m];
        float pv = ex2f_(fp2 + fmaf(ppx,c.x, fmaf(ppy,c.y, fmaf(ppz,c.z, c.w))));
        if (m == l) pv *= E005;
        po[m] = pv;
        tx = fmaf(pv, c.x, tx);
        ty = fmaf(pv, c.y, ty);
        tz = fmaf(pv, c.z, tz);
    }
    #pragma unroll
    for (int o = 16; o; o >>= 1){
        tx += __shfl_xor_sync(0xFFFFFFFFu, tx, o);
        ty += __shfl_xor_sync(0xFFFFFFFFu, ty, o);
        tz += __shfl_xor_sync(0xFFFFFFFFu, tz, o);
    }
    if (lane == 0){
        float* tp = tpmout + (size_t)(n*LL + l)*3;
        tp[0] = tx; tp[1] = ty; tp[2] = tz;
    }
}

// ---------------- Kabsch + 3x3 SVD (per batch) ----------------
__global__ void k_kabsch(const float* __restrict__ pred, const float* __restrict__ tpm){
    int n = blockIdx.x, tid = threadIdx.x;
    float s[15];
    #pragma unroll
    for (int k = 0; k < 15; k++) s[k] = 0.f;
    for (int l = tid; l < LL; l += 256){
        const float* p = pred + (size_t)(n*LL + l)*3;
        const float* q = tpm  + (size_t)(n*LL + l)*3;
        float p0=p[0],p1=p[1],p2=p[2], q0=q[0],q1=q[1],q2=q[2];
        s[0]+=p0; s[1]+=p1; s[2]+=p2; s[3]+=q0; s[4]+=q1; s[5]+=q2;
        s[6]+=p0*q0;  s[7]+=p0*q1;  s[8]+=p0*q2;
        s[9]+=p1*q0;  s[10]+=p1*q1; s[11]+=p1*q2;
        s[12]+=p2*q0; s[13]+=p2*q1; s[14]+=p2*q2;
    }
    __shared__ float red[256];
    __shared__ float tot[15];
    for (int k = 0; k < 15; k++){
        red[tid] = s[k]; __syncthreads();
        for (int st = 128; st; st >>= 1){
            if (tid < st) red[tid] += red[tid+st];
            __syncthreads();
        }
        if (tid == 0) tot[k] = red[0];
        __syncthreads();
    }
    if (tid != 0) return;

    double w = fmax((double)g_cnt[n], 1e-6);
    double cp[3] = { tot[0]/w, tot[1]/w, tot[2]/w };
    double cq[3] = { tot[3]/w, tot[4]/w, tot[5]/w };
    double H[3][3];
    for (int i = 0; i < 3; i++)
        for (int j = 0; j < 3; j++)
            H[i][j] = (double)tot[6 + 3*i + j] - w*cp[i]*cq[j];

    double fn = 0.0;
    for (int i = 0; i < 3; i++) for (int j = 0; j < 3; j++) fn += H[i][j]*H[i][j];
    fn = fmax(sqrt(fn), 1e-8);
    double M[3][3];
    for (int i = 0; i < 3; i++)
        for (int j = 0; j < 3; j++)
            M[i][j] = H[i][j]/fn + (i==j ? 1e-4 : 0.0);

    double B[3][3];
    for (int i = 0; i < 3; i++)
        for (int j = 0; j < 3; j++){
            double acc = 0.0;
            for (int k = 0; k < 3; k++) acc += M[k][i]*M[k][j];
            B[i][j] = acc;
        }
    double V[3][3] = {{1,0,0},{0,1,0},{0,0,1}};
    for (int sw = 0; sw < 15; sw++){
        for (int pair = 0; pair < 3; pair++){
            int p = (pair==2) ? 1 : 0;
            int q = (pair==0) ? 1 : 2;
            double apq = B[p][q];
            if (fabs(apq) < 1e-30) continue;
            double tau = (B[q][q] - B[p][p])/(2.0*apq);
            double t = ((tau >= 0.0) ? 1.0 : -1.0)/(fabs(tau) + sqrt(1.0 + tau*tau));
            double c = 1.0/sqrt(1.0 + t*t), sn = t*c;
            for (int k = 0; k < 3; k++){
                double bkp = B[k][p], bkq = B[k][q];
                B[k][p] = c*bkp - sn*bkq; B[k][q] = sn*bkp + c*bkq;
            }
            for (int k = 0; k < 3; k++){
                double bpk = B[p][k], bqk = B[q][k];
                B[p][k] = c*bpk - sn*bqk; B[q][k] = sn*bpk + c*bqk;
            }
            for (int k = 0; k < 3; k++){
                double vkp = V[k][p], vkq = V[k][q];
                V[k][p] = c*vkp - sn*vkq; V[k][q] = sn*vkp + c*vkq;
            }
        }
    }
    double lam[3] = { B[0][0], B[1][1], B[2][2] };
    for (int i = 0; i < 2; i++)
        for (int j = 0; j < 2 - i; j++)
            if (lam[j] < lam[j+1]){
                double tl = lam[j]; lam[j] = lam[j+1]; lam[j+1] = tl;
                for (int k = 0; k < 3; k++){ double tv = V[k][j]; V[k][j] = V[k][j+1]; V[k][j+1] = tv; }
            }
    double detV = V[0][0]*(V[1][1]*V[2][2]-V[1][2]*V[2][1])
                - V[0][1]*(V[1][0]*V[2][2]-V[1][2]*V[2][0])
                + V[0][2]*(V[1][0]*V[2][1]-V[1][1]*V[2][0]);
    if (detV < 0.0) for (int k = 0; k < 3; k++) V[k][2] = -V[k][2];

    double s1 = sqrt(fmax(lam[0], 0.0)), s2 = sqrt(fmax(lam[1], 0.0));
    double u1[3], u2[3], u3[3];
    for (int k = 0; k < 3; k++){
        u1[k] = (M[k][0]*V[0][0] + M[k][1]*V[1][0] + M[k][2]*V[2][0]) / fmax(s1, 1e-30);
        u2[k] = (M[k][0]*V[0][1] + M[k][1]*V[1][1] + M[k][2]*V[2][1]) / fmax(s2, 1e-30);
    }
    double n1 = sqrt(u1[0]*u1[0]+u1[1]*u1[1]+u1[2]*u1[2]);
    for (int k = 0; k < 3; k++) u1[k] /= fmax(n1, 1e-30);
    double d12 = u1[0]*u2[0]+u1[1]*u2[1]+u1[2]*u2[2];
    for (int k = 0; k < 3; k++) u2[k] -= d12*u1[k];
    double n2 = sqrt(u2[0]*u2[0]+u2[1]*u2[1]+u2[2]*u2[2]);
    for (int k = 0; k < 3; k++) u2[k] /= fmax(n2, 1e-30);
    u3[0] = u1[1]*u2[2] - u1[2]*u2[1];
    u3[1] = u1[2]*u2[0] - u1[0]*u2[2];
    u3[2] = u1[0]*u2[1] - u1[1]*u2[0];

    for (int d = 0; d < 3; d++)
        for (int e = 0; e < 3; e++)
            g_R[n][3*d + e] = (float)(u1[d]*V[e][0] + u2[d]*V[e][1] + u3[d]*V[e][2]);
    for (int k = 0; k < 3; k++){ g_cp[n][k] = (float)cp[k]; g_ct[n][k] = (float)cq[k]; }
}

// ---------------- TM score ----------------
__global__ void k_tm(const float* __restrict__ pred, const float* __restrict__ mgen,
                     const float* __restrict__ tpm, float* __restrict__ avg, float inv_d02){
    int n = blockIdx.x, tid = threadIdx.x;
    float R[9];
    #pragma unroll
    for (int k = 0; k < 9; k++) R[k] = g_R[n][k];
    float cp0 = g_cp[n][0], cp1 = g_cp[n][1], cp2 = g_cp[n][2];
    float ct0 = g_ct[n][0], ct1 = g_ct[n][1], ct2 = g_ct[n][2];

    float st = 0.f, sm = 0.f;
    for (int l = tid; l < LL; l += 256){
        const float* p = pred + (size_t)(n*LL + l)*3;
        const float* q = tpm  + (size_t)(n*LL + l)*3;
        float x0 = p[0]-cp0, x1 = p[1]-cp1, x2 = p[2]-cp2;
        float a0 = x0*R[0] + x1*R[3] + x2*R[6] + ct0;
        float a1 = x0*R[1] + x1*R[4] + x2*R[7] + ct1;
        float a2 = x0*R[2] + x1*R[5] + x2*R[8] + ct2;
        float d0 = a0-q[0], d1 = a1-q[1], d2 = a2-q[2];
        float dsq = d0*d0 + d1*d1 + d2*d2;
        float tm = 1.f/(1.f + dsq*inv_d02);
        float mg = mgen[n*LL + l];
        st += tm*mg; sm += mg;
    }
    __shared__ float r1[256], r2[256];
    r1[tid] = st; r2[tid] = sm; __syncthreads();
    for (int s = 128; s; s >>= 1){
        if (tid < s){ r1[tid] += r1[tid+s]; r2[tid] += r2[tid+s]; }
        __syncthreads();
    }
    if (tid == 0) avg[n] = r1[0] / fmaxf(r2[0], 1e-6f);
}

// ---------------- launch ----------------
extern "C" void kernel_launch(void* const* d_in, const int* in_sizes, int n_in,
                              void* d_out, int out_size){
    const float* pred = (const float*)d_in[0];
    const float* tru  = (const float*)d_in[1];
    const float* mgen = (const float*)d_in[2];

    float* out   = (float*)d_out;
    float* avg   = out;                       // (N,)
    float* tpm   = out + NB;                  // (N,L,3)
    float* piout = out + NB + (size_t)NL*3;   // (N,L,L)

    k_zero<<<1, 32>>>();
    k_prep<<<NL/256, 256>>>(pred, tru, mgen);
    k_prep2<<<1, 32>>>();

    k_exp<<<1024, 256>>>();                   // build K once (only exp-heavy pass)

    for (int it = 0; it < 10; it++){
        k_mvf<<<1024, 256>>>();               // u = a / (K v)
        k_mvg<<<1024, 256>>>();               // v = b / (K^T u)
    }

    k_fg<<<NL/256, 256>>>();
    k_pi<<<1024, 512>>>(piout, tpm);
    k_kabsch<<<NB, 256>>>(pred, tpm);

    double d0 = 1.24 * cbrt((double)((LL > 16 ? LL : 16) - 15)) - 1.8;
    if (d0 < 0.5) d0 = 0.5;
    float inv_d02 = (float)(1.0/(d0*d0));
    k_tm<<<NB, 256>>>(pred, mgen, tpm, avg, inv_d02);
}